// round 2
// baseline (speedup 1.0000x reference)
#include <cuda_runtime.h>
#include <cuda_bf16.h>

// out[b,n] = sum_m x[b,n,m] * w1[m,0,n] + b1[0,n,0]
// x:  [B, N, M]  = [256, 4096, 64]  (m contiguous, 256B per row)
// w1: [M, 1, N]  = [64, 1, 4096]    (n contiguous, stride N per m)
// b1: [1, N, 1]  = [4096]
// out:[B, N]     = [256, 4096]
//
// Warp-cooperative: 16 lanes per (b,n) row, lane loads one float4.
// A warp covers rows (n0, n0+1) which are CONTIGUOUS 512B in x ->
// every x LDG.128 is exactly 4 fully-used 128B wavefronts (coalesced).
// Each block loops over a 32-wide b-chunk with its 4 w values cached
// in registers, so w DRAM traffic is negligible. shfl_xor butterfly
// reduction; lane 0 emits a coalesced float2 per b.

#define N_DIM   4096
#define B_DIM   256
#define B_CHUNK 32
#define ROW_F4  16              // 64 floats per row = 16 float4
#define B_STRIDE_F4 (N_DIM * ROW_F4)   // float4 stride between batches

__global__ __launch_bounds__(256) void superlinear_kernel(
    const float*  __restrict__ x,
    const float*  __restrict__ w,
    const float*  __restrict__ bias,
    float*        __restrict__ out)
{
    const int warp = threadIdx.x >> 5;
    const int lane = threadIdx.x & 31;
    const int half = lane >> 4;          // 0 or 1 -> which n of the pair
    const int sub  = lane & 15;          // position within the row

    const int n_pair = blockIdx.x * 16 + warp * 2;   // even n for this warp
    const int n      = n_pair + half;
    const int b0     = blockIdx.y * B_CHUNK;

    // Cache this lane's 4 weights (w[4*sub + j][n]) and the bias.
    const int m0 = sub * 4;
    const float w0 = __ldg(&w[(m0 + 0) * N_DIM + n]);
    const float w1v = __ldg(&w[(m0 + 1) * N_DIM + n]);
    const float w2 = __ldg(&w[(m0 + 2) * N_DIM + n]);
    const float w3 = __ldg(&w[(m0 + 3) * N_DIM + n]);
    const float bv = __ldg(&bias[n]);

    // This lane's float4 within row (b, n): x + (b*N + n)*64 + sub*4
    const float4* __restrict__ xr =
        (const float4*)(x + ((size_t)b0 * N_DIM + n) * 64) + sub;

    float* __restrict__ orow = out + (size_t)b0 * N_DIM + n_pair;

    #pragma unroll 2
    for (int i = 0; i < B_CHUNK; i += 4) {
        // 4 independent batches in flight (16 KB apart) for MLP.
        const float4 a0 = xr[(size_t)(i + 0) * B_STRIDE_F4];
        const float4 a1 = xr[(size_t)(i + 1) * B_STRIDE_F4];
        const float4 a2 = xr[(size_t)(i + 2) * B_STRIDE_F4];
        const float4 a3 = xr[(size_t)(i + 3) * B_STRIDE_F4];

        float p0 = a0.x * w0; p0 = fmaf(a0.y, w1v, p0);
        p0 = fmaf(a0.z, w2, p0); p0 = fmaf(a0.w, w3, p0);
        float p1 = a1.x * w0; p1 = fmaf(a1.y, w1v, p1);
        p1 = fmaf(a1.z, w2, p1); p1 = fmaf(a1.w, w3, p1);
        float p2 = a2.x * w0; p2 = fmaf(a2.y, w1v, p2);
        p2 = fmaf(a2.z, w2, p2); p2 = fmaf(a2.w, w3, p2);
        float p3 = a3.x * w0; p3 = fmaf(a3.y, w1v, p3);
        p3 = fmaf(a3.z, w2, p3); p3 = fmaf(a3.w, w3, p3);

        // Butterfly reduce within each 16-lane half; every lane gets the sum.
        #pragma unroll
        for (int s = 8; s >= 1; s >>= 1) {
            p0 += __shfl_xor_sync(0xffffffffu, p0, s);
            p1 += __shfl_xor_sync(0xffffffffu, p1, s);
            p2 += __shfl_xor_sync(0xffffffffu, p2, s);
            p3 += __shfl_xor_sync(0xffffffffu, p3, s);
        }

        p0 += bv; p1 += bv; p2 += bv; p3 += bv;

        // lane 0 holds n_pair's value; pull n_pair+1 from lane 16, store float2.
        const float q0 = __shfl_sync(0xffffffffu, p0, 16);
        const float q1 = __shfl_sync(0xffffffffu, p1, 16);
        const float q2 = __shfl_sync(0xffffffffu, p2, 16);
        const float q3 = __shfl_sync(0xffffffffu, p3, 16);

        if (lane == 0) {
            *(float2*)(orow + (size_t)(i + 0) * N_DIM) = make_float2(p0, q0);
            *(float2*)(orow + (size_t)(i + 1) * N_DIM) = make_float2(p1, q1);
            *(float2*)(orow + (size_t)(i + 2) * N_DIM) = make_float2(p2, q2);
            *(float2*)(orow + (size_t)(i + 3) * N_DIM) = make_float2(p3, q3);
        }
    }
}

extern "C" void kernel_launch(void* const* d_in, const int* in_sizes, int n_in,
                              void* d_out, int out_size)
{
    const float* x    = (const float*)d_in[0];   // [256, 4096, 64]
    const float* w1   = (const float*)d_in[1];   // [64, 1, 4096]
    const float* b1   = (const float*)d_in[2];   // [1, 4096, 1]
    float*       out  = (float*)d_out;           // [256, 4096]

    dim3 block(256);                              // 8 warps -> 16 n per block
    dim3 grid(N_DIM / 16, B_DIM / B_CHUNK);       // (256, 8) = 2048 blocks
    superlinear_kernel<<<grid, block>>>(x, w1, b1, out);
}